// round 1
// baseline (speedup 1.0000x reference)
#include <cuda_runtime.h>
#include <math.h>

// Problem constants
#define BN 4
#define CN 64
#define HN 128
#define WN 128
#define ON 64
#define K2C 9
#define HW (HN*WN)
#define CK 576          // CN * K2C

// ---------------- scratch (no allocs allowed) ----------------
__device__ __align__(16) float g_sy[BN*K2C*HW];   // sample y coords
__device__ __align__(16) float g_sx[BN*K2C*HW];   // sample x coords
__device__ __align__(16) float g_mm[BN*HW];       // mean sigmoid modulation
__device__ __align__(16) float g_wT[K2C*CN*ON];   // main weight as [k][c][o]
__device__ __align__(16) float g_wA[CK*28];       // offset+mod weight as [c*9+tap][28] (27 ch + 1 zero pad)

// ---------------- f32x2 helpers (packed fp32 = 2x FFMA rate on sm_103a) ----------------
__device__ __forceinline__ unsigned long long pack2(float lo, float hi){
  unsigned long long r; asm("mov.b64 %0, {%1,%2};" : "=l"(r) : "f"(lo), "f"(hi)); return r;
}
__device__ __forceinline__ void unpack2(unsigned long long v, float& lo, float& hi){
  asm("mov.b64 {%0,%1}, %2;" : "=f"(lo), "=f"(hi) : "l"(v));
}
__device__ __forceinline__ void ffma2(unsigned long long& d, unsigned long long a, unsigned long long b){
  asm("fma.rn.f32x2 %0, %1, %2, %0;" : "+l"(d) : "l"(a), "l"(b));
}

// ---------------- kernel 0: weight reshuffles ----------------
__global__ void prep_weights(const float* __restrict__ weight,
                             const float* __restrict__ offw,
                             const float* __restrict__ modw){
  int i = blockIdx.x*blockDim.x + threadIdx.x;
  if (i < K2C*CN*ON){
    int o = i & 63, c = (i >> 6) & 63, k = i >> 12;
    g_wT[i] = weight[(o*CN + c)*K2C + k];
  }
  if (i < CK*28){
    int ch = i % 28, ct = i / 28;          // ct = c*9 + tap
    float v = 0.f;
    if (ch < 18)      v = offw[ch*CK + ct];
    else if (ch < 27) v = modw[(ch-18)*CK + ct];
    g_wA[i] = v;
  }
}

// ---------------- kernel 1: offset + modulation conv ----------------
__device__ __forceinline__ void write_pix(int b, int ho, int wo,
                                          const float* __restrict__ offb,
                                          const float* __restrict__ modb,
                                          const float (&rr)[28]){
  float msum = 0.f;
  #pragma unroll
  for (int k = 0; k < 9; k++){
    float kyf = (float)(k/3) - 1.f;
    float kxf = (float)(k%3) - 1.f;
    int idx = ((b*9 + k)*HN + ho)*WN + wo;
    g_sy[idx] = (float)ho + kyf + rr[k]     + offb[k];
    g_sx[idx] = (float)wo + kxf + rr[9 + k] + offb[9 + k];
    float z = rr[18 + k] + modb[k];
    msum += 1.f / (1.f + expf(-z));
  }
  g_mm[(b*HN + ho)*WN + wo] = msum * (1.f/9.f);
}

__global__ __launch_bounds__(256)
void offset_kernel(const float* __restrict__ x,
                   const float* __restrict__ offb,
                   const float* __restrict__ modb){
  extern __shared__ unsigned long long wsmA[];   // CK * 14 u64 = 63 KB
  {
    float4* dst = (float4*)wsmA;
    const float4* src = (const float4*)g_wA;
    for (int i = threadIdx.x; i < CK*28/4; i += 256) dst[i] = src[i];
  }
  __syncthreads();

  const int b   = blockIdx.y;
  const int wo  = threadIdx.x & 127;
  const int rh  = threadIdx.x >> 7;
  const int ho0 = blockIdx.x*4 + rh*2;           // this thread: pixels (ho0,wo) and (ho0+1,wo)
  const float* xb = x + b*CN*HW;

  unsigned long long acc0[14], acc1[14];
  #pragma unroll
  for (int j = 0; j < 14; j++){ acc0[j] = 0ull; acc1[j] = 0ull; }

  const bool cok0 = (wo - 1) >= 0;
  const bool cok2 = (wo + 1) < WN;

  for (int c = 0; c < CN; ++c){
    const float* xc = xb + c*HW;
    float xv[4][3];
    #pragma unroll
    for (int r = 0; r < 4; r++){
      int row = ho0 - 1 + r;
      bool rok = (row >= 0) && (row < HN);
      const float* xr = xc + row*WN;
      xv[r][0] = (rok && cok0) ? xr[wo-1] : 0.f;
      xv[r][1] =  rok          ? xr[wo]   : 0.f;
      xv[r][2] = (rok && cok2) ? xr[wo+1] : 0.f;
    }
    #pragma unroll
    for (int ky = 0; ky < 3; ky++){
      #pragma unroll
      for (int kx = 0; kx < 3; kx++){
        const int tap = ky*3 + kx;
        unsigned long long a0 = pack2(xv[ky  ][kx], xv[ky  ][kx]);
        unsigned long long a1 = pack2(xv[ky+1][kx], xv[ky+1][kx]);
        const unsigned long long* wp = wsmA + (c*9 + tap)*14;   // uniform addr -> broadcast LDS
        #pragma unroll
        for (int j = 0; j < 14; j++){
          unsigned long long w2 = wp[j];
          ffma2(acc0[j], w2, a0);
          ffma2(acc1[j], w2, a1);
        }
      }
    }
  }

  float r0[28], r1[28];
  #pragma unroll
  for (int j = 0; j < 14; j++){
    unpack2(acc0[j], r0[2*j], r0[2*j+1]);
    unpack2(acc1[j], r1[2*j], r1[2*j+1]);
  }
  write_pix(b, ho0,     wo, offb, modb, r0);
  write_pix(b, ho0 + 1, wo, offb, modb, r1);
}

// ---------------- kernel 2: bilinear sample + implicit GEMM + epilogue ----------------
__global__ __launch_bounds__(256)
void deform_kernel(const float* __restrict__ x,
                   const float* __restrict__ bias,
                   float* __restrict__ out){
  __shared__ unsigned long long ssm[CN*64];   // sampled values, pre-duplicated f32x2 (32 KB)
  __shared__ float wsm[CN*ON];                // weight slice [c][o] for current tap (16 KB)

  const int b   = blockIdx.z;
  const int ho  = blockIdx.y;
  const int wo0 = blockIdx.x * 64;
  const int tid = threadIdx.x;
  const int p_s = tid & 63;      // sampling: pixel
  const int cg  = tid >> 6;      // sampling: channel group (16 ch each)
  const int to  = tid & 15;      // gemm: o-quad
  const int tp  = tid >> 4;      // gemm: p-quad
  const float* xb = x + b*CN*HW;

  unsigned long long acc[2][4];  // [o-pair][p]; lo half -> o0+2j, hi half -> o0+2j+1
  #pragma unroll
  for (int j = 0; j < 2; j++)
    #pragma unroll
    for (int p = 0; p < 4; p++) acc[j][p] = 0ull;

  const int wo = wo0 + p_s;

  for (int k = 0; k < 9; k++){
    if (k) __syncthreads();      // previous GEMM must be done before smem overwrite

    // stage weight slice [c][o] for this tap
    {
      const float4* wsrc = (const float4*)(g_wT + k*CN*ON);
      float4* wdst = (float4*)wsm;
      #pragma unroll
      for (int i = 0; i < 4; i++) wdst[tid + i*256] = wsrc[tid + i*256];
    }

    // bilinear sample 16 channels for my pixel into ssm (duplicated for f32x2)
    {
      int sidx = ((b*9 + k)*HN + ho)*WN + wo;
      float sy = g_sy[sidx], sx = g_sx[sidx];
      float y0f = floorf(sy), x0f = floorf(sx);
      float wy1 = sy - y0f, wx1 = sx - x0f;
      float wy0 = 1.f - wy1, wx0 = 1.f - wx1;
      int y0 = (int)y0f, x0i = (int)x0f;
      int y1 = y0 + 1,  x1i = x0i + 1;
      float my0 = (y0  >= 0 && y0  < HN) ? 1.f : 0.f;
      float my1 = (y1  >= 0 && y1  < HN) ? 1.f : 0.f;
      float mx0 = (x0i >= 0 && x0i < WN) ? 1.f : 0.f;
      float mx1 = (x1i >= 0 && x1i < WN) ? 1.f : 0.f;
      int cy0 = min(max(y0, 0), HN-1),  cy1 = min(max(y1, 0), HN-1);
      int cx0 = min(max(x0i, 0), WN-1), cx1 = min(max(x1i, 0), WN-1);
      int i00 = cy0*WN + cx0, i01 = cy0*WN + cx1;
      int i10 = cy1*WN + cx0, i11 = cy1*WN + cx1;
      float w00 = wy0*wx0*my0*mx0, w01 = wy0*wx1*my0*mx1;
      float w10 = wy1*wx0*my1*mx0, w11 = wy1*wx1*my1*mx1;
      const float* xc = xb + cg*16*HW;
      #pragma unroll
      for (int i = 0; i < 16; i++){
        float v = w00*xc[i00] + w01*xc[i01] + w10*xc[i10] + w11*xc[i11];
        ssm[(cg*16 + i)*64 + p_s] = pack2(v, v);
        xc += HW;
      }
    }
    __syncthreads();

    // GEMM: 4o x 4p per thread, packed f32x2 FMAs
    #pragma unroll 8
    for (int c = 0; c < CN; c++){
      ulonglong2 wv  = *(const ulonglong2*)&wsm[c*ON + to*4];     // {w0,w1},{w2,w3}
      ulonglong2 s01 = *(const ulonglong2*)&ssm[c*64 + tp*4];     // dup(s0),dup(s1)
      ulonglong2 s23 = *(const ulonglong2*)&ssm[c*64 + tp*4 + 2]; // dup(s2),dup(s3)
      ffma2(acc[0][0], wv.x, s01.x);
      ffma2(acc[0][1], wv.x, s01.y);
      ffma2(acc[0][2], wv.x, s23.x);
      ffma2(acc[0][3], wv.x, s23.y);
      ffma2(acc[1][0], wv.y, s01.x);
      ffma2(acc[1][1], wv.y, s01.y);
      ffma2(acc[1][2], wv.y, s23.x);
      ffma2(acc[1][3], wv.y, s23.y);
    }
  }

  // epilogue: * mod_mean + bias
  float4 mm4 = *(const float4*)&g_mm[(b*HN + ho)*WN + wo0 + tp*4];
  float mmv[4] = {mm4.x, mm4.y, mm4.z, mm4.w};
  #pragma unroll
  for (int j = 0; j < 2; j++){
    float lo[4], hi[4];
    #pragma unroll
    for (int p = 0; p < 4; p++) unpack2(acc[j][p], lo[p], hi[p]);
    int olo = to*4 + 2*j;
    float blo = bias[olo], bhi = bias[olo + 1];
    float4 rlo = make_float4(lo[0]*mmv[0]+blo, lo[1]*mmv[1]+blo, lo[2]*mmv[2]+blo, lo[3]*mmv[3]+blo);
    float4 rhi = make_float4(hi[0]*mmv[0]+bhi, hi[1]*mmv[1]+bhi, hi[2]*mmv[2]+bhi, hi[3]*mmv[3]+bhi);
    *(float4*)&out[((b*ON + olo    )*HN + ho)*WN + wo0 + tp*4] = rlo;
    *(float4*)&out[((b*ON + olo + 1)*HN + ho)*WN + wo0 + tp*4] = rhi;
  }
}

// ---------------- launch ----------------
extern "C" void kernel_launch(void* const* d_in, const int* in_sizes, int n_in,
                              void* d_out, int out_size) {
  const float* x      = (const float*)d_in[0];
  const float* weight = (const float*)d_in[1];
  const float* bias   = (const float*)d_in[2];
  const float* offw   = (const float*)d_in[3];
  const float* offb   = (const float*)d_in[4];
  const float* modw   = (const float*)d_in[5];
  const float* modb   = (const float*)d_in[6];
  float* out = (float*)d_out;

  cudaFuncSetAttribute(offset_kernel, cudaFuncAttributeMaxDynamicSharedMemorySize, CK*28*4);

  prep_weights<<<144, 256>>>(weight, offw, modw);
  offset_kernel<<<dim3(32, BN), 256, CK*28*4>>>(x, offb, modb);
  deform_kernel<<<dim3(2, HN, BN), 256>>>(x, bias, out);
}